// round 17
// baseline (speedup 1.0000x reference)
#include <cuda_runtime.h>

// VanillaRNN persistent kernel for GB300 (sm_103a) — round 16: warp-private refresh.
// h_{t+1} = tanh(W_hx * x_t + W_hh @ h_t + b_h), 1024 steps; p = W_ph @ h + b_p.
//
// 256 persistent CTAs = 32 rg x 8 bg; 16 rows x 32 cols; 256 thr; 2 CTAs/SM.
// R15 core (FFMA2, v2.u64 broadcast h, per-tile flags, triple buffer) with the
// refresh made WARP-PRIVATE: warp w's k-slice [64w,64w+64) = exactly producer
// row-groups 4w..4w+3, so warp w polls those 4 flags (lanes 0-3) and loads its
// own hs rows, then flows straight into compute -- NO pre-compute block sync.
// hs is warp-private (writer == only reader). Block syncs: 3 -> 2 per step.

#define HH    512
#define BB    256
#define TT    1024
#define NCLS  10

#define RGN   32
#define BGN   8
#define HR    16
#define BT    32
#define NCTA  (RGN * BGN)   // 256
#define NTHR  256
#define NW    8

#define H_PAD 36
#define CSTR  36

#define SMEM_FLOATS (HH * H_PAD + NW * HR * CSTR + BT)
#define SMEM_BYTES  (SMEM_FLOATS * 4)     // 92,288 B -> 2 CTAs/SM

typedef unsigned long long u64;

__device__ float    g_h[3][HH][BB];        // triple-buffered hidden state
__device__ unsigned g_flag[BGN][RGN][32];  // per-tile publish counters, 128B apart

__device__ __forceinline__ void wait_flag(const unsigned* p, unsigned target) {
    unsigned v;
    do {
        asm volatile("ld.acquire.gpu.u32 %0, [%1];" : "=r"(v) : "l"(p) : "memory");
    } while (v < target);
}

__device__ __forceinline__ u64 ffma2(u64 a, u64 b, u64 c) {
    u64 d;
    asm("fma.rn.f32x2 %0, %1, %2, %3;" : "=l"(d) : "l"(a), "l"(b), "l"(c));
    return d;
}

__global__ void __launch_bounds__(NTHR, 2) rnn_persistent(
    const float* __restrict__ x,       // [BB][TT]
    const float* __restrict__ h_init,  // [HH]
    const float* __restrict__ W_hx,    // [HH]
    const float* __restrict__ W_hh,    // [HH][HH]
    const float* __restrict__ b_h,     // [HH]
    const float* __restrict__ W_ph,    // [NCLS][HH]
    const float* __restrict__ b_p,     // [NCLS]
    float* __restrict__ out)           // [BB][NCLS]
{
    extern __shared__ float smem[];
    float* hs  = smem;                        // [HH][H_PAD]
    float* red = smem + HH * H_PAD;           // [NW*HR][CSTR]
    float* xs  = red + NW * HR * CSTR;        // [BT]

    const int tid   = threadIdx.x;
    const int lane  = tid & 31;
    const int wid   = tid >> 5;        // 0..7 : 64-wide k-slice
    const int cta   = blockIdx.x;
    const int rg    = cta >> 3;        // 0..31
    const int bg    = cta & 7;
    const int rbase = rg * HR;
    const int cbase = bg * BT;
    const int k0    = wid << 6;        // 64*wid

    // ---- lane decomposition ----
    const int rp = lane & 7;           // row pair
    const int kh = (lane >> 3) & 1;    // k parity
    const int ch = lane >> 4;          // col half
    const int r0 = rp << 1;            // local rows r0, r0+1
    const int cb = ch << 4;            // local col base (16 cols)

    // ---- W_hh -> registers: 2 rows x 32 k (k = k0 + 2i + kh) ----
    float w0[32], w1[32];
    {
        const float* wr0 = W_hh + (rbase + r0)     * HH + k0 + kh;
        const float* wr1 = W_hh + (rbase + r0 + 1) * HH + k0 + kh;
        #pragma unroll
        for (int i = 0; i < 32; ++i) {
            w0[i] = wr0[i << 1];
            w1[i] = wr1[i << 1];
        }
    }

    // ---- init hs with h_init broadcast ----
    for (int k = tid; k < HH; k += NTHR) {
        float v = h_init[k];
        float* row = hs + k * H_PAD;
        #pragma unroll
        for (int c = 0; c < BT; ++c) row[c] = v;
    }

    // ---- reduce/publish mapping: thread -> (row ro 0..15, col pair cp) ----
    const int ro = tid >> 4;            // 0..15
    const int cp = (tid & 15) << 1;     // 0,2,...,30
    const float bh = b_h[rbase + ro];
    const float wx = W_hx[rbase + ro];

    // ---- warp-private refresh mapping: warp wid owns chunks 4wid..4wid+3 ----
    const int lk  = lane >> 3;          // 0..3
    const int lc4 = (lane & 7) << 2;    // 0,4,...,28

    const unsigned hb_s =
        (unsigned)__cvta_generic_to_shared(hs + (k0 + kh) * H_PAD + cb);

    __syncthreads();

    for (int s = 0; s < TT; ++s) {
        // ---- warp-private refresh of own k-slice rows (skip s=0) ----
        if (s > 0) {
            const int rbuf = s % 3;
            if (lane < 4)
                wait_flag(&g_flag[bg][(wid << 2) + lane][0], (unsigned)s);
            __syncwarp();
            #pragma unroll
            for (int t = 0; t < 4; ++t) {
                const int j = (wid << 2) + t;
                const float* src = &g_h[rbuf][j << 4][cbase];
                float*       dst = hs + (j << 4) * H_PAD;
                #pragma unroll
                for (int p = 0; p < 4; ++p) {
                    int k = (p << 2) + lk;
                    float4 v = __ldcg(reinterpret_cast<const float4*>(src + k * BB + lc4));
                    *reinterpret_cast<float4*>(dst + k * H_PAD + lc4) = v;
                }
            }
            __syncwarp();
        }
        if (tid < BT) xs[tid] = x[(cbase + tid) * TT + s];

        // ---- packed partial GEMV: 2 rows x 32 k x 16 cols via FFMA2 ----
        u64 P0[8], P1[8];
        #pragma unroll
        for (int q = 0; q < 8; ++q) { P0[q] = 0ull; P1[q] = 0ull; }

        #pragma unroll
        for (int i = 0; i < 32; ++i) {
            u64 dw0, dw1;
            asm("mov.b64 %0, {%1, %1};" : "=l"(dw0) : "f"(w0[i]));
            asm("mov.b64 %0, {%1, %1};" : "=l"(dw1) : "f"(w1[i]));
            const unsigned hr = hb_s + (unsigned)((i << 1) * (H_PAD * 4));
            #pragma unroll
            for (int q = 0; q < 4; ++q) {
                u64 hA, hB;
                asm("ld.shared.v2.u64 {%0, %1}, [%2];"
                    : "=l"(hA), "=l"(hB) : "r"(hr + (q << 4)));
                P0[2*q]     = ffma2(dw0, hA, P0[2*q]);
                P0[2*q + 1] = ffma2(dw0, hB, P0[2*q + 1]);
                P1[2*q]     = ffma2(dw1, hA, P1[2*q]);
                P1[2*q + 1] = ffma2(dw1, hB, P1[2*q + 1]);
            }
        }

        // ---- unpack, combine kh halves (partner = lane ^ 8), STS keep-row ----
        float4 A0[4], A1[4];
        #pragma unroll
        for (int q = 0; q < 4; ++q) {
            asm("mov.b64 {%0, %1}, %2;" : "=f"(A0[q].x), "=f"(A0[q].y) : "l"(P0[2*q]));
            asm("mov.b64 {%0, %1}, %2;" : "=f"(A0[q].z), "=f"(A0[q].w) : "l"(P0[2*q+1]));
            asm("mov.b64 {%0, %1}, %2;" : "=f"(A1[q].x), "=f"(A1[q].y) : "l"(P1[2*q]));
            asm("mov.b64 {%0, %1}, %2;" : "=f"(A1[q].z), "=f"(A1[q].w) : "l"(P1[2*q+1]));
        }

        const int myrow = r0 + kh;
        float* myred = red + ((wid << 4) + myrow) * CSTR + cb;
        #pragma unroll
        for (int q = 0; q < 4; ++q) {
            float4 send = kh ? A0[q] : A1[q];
            float4 keep = kh ? A1[q] : A0[q];
            float4 rec;
            rec.x = __shfl_xor_sync(0xffffffffu, send.x, 8);
            rec.y = __shfl_xor_sync(0xffffffffu, send.y, 8);
            rec.z = __shfl_xor_sync(0xffffffffu, send.z, 8);
            rec.w = __shfl_xor_sync(0xffffffffu, send.w, 8);
            keep.x += rec.x; keep.y += rec.y; keep.z += rec.z; keep.w += rec.w;
            *reinterpret_cast<float4*>(myred + (q << 2)) = keep;
        }
        __syncthreads();

        // ---- reduce 8 k-slice partials (LDS.64), finish, publish ----
        {
            const float* rr = red + ro * CSTR + cp;
            float s0 = 0.f, s1 = 0.f;
            #pragma unroll
            for (int w = 0; w < 8; ++w) {
                float2 p = *reinterpret_cast<const float2*>(rr + (w << 4) * CSTR);
                s0 += p.x; s1 += p.y;
            }
            float v0 = tanhf(s0 + fmaf(wx, xs[cp],     bh));
            float v1 = tanhf(s1 + fmaf(wx, xs[cp + 1], bh));
            const int wbuf = (s + 1) % 3;
            *reinterpret_cast<float2*>(&g_h[wbuf][rbase + ro][cbase + cp]) =
                make_float2(v0, v1);
        }

        __syncthreads();
        if (tid == 0)
            asm volatile("st.release.gpu.u32 [%0], %1;"
                         :: "l"(&g_flag[bg][rg][0]), "r"((unsigned)(s + 1)) : "memory");
    }

    // ---- final projection (row-group 0 CTAs); h_1024 in buf 1024%3 == 1 ----
    if (rg == 0) {
        {
            const int rbuf = TT % 3;
            if (lane < 4)
                wait_flag(&g_flag[bg][(wid << 2) + lane][0], (unsigned)TT);
            __syncwarp();
            #pragma unroll
            for (int t = 0; t < 4; ++t) {
                const int j = (wid << 2) + t;
                const float* src = &g_h[rbuf][j << 4][cbase];
                float*       dst = hs + (j << 4) * H_PAD;
                #pragma unroll
                for (int p = 0; p < 4; ++p) {
                    int k = (p << 2) + lk;
                    float4 v = __ldcg(reinterpret_cast<const float4*>(src + k * BB + lc4));
                    *reinterpret_cast<float4*>(dst + k * H_PAD + lc4) = v;
                }
            }
        }
        __syncthreads();

        for (int idx = tid; idx < BT * NCLS; idx += NTHR) {
            int cl = idx / NCLS;
            int n  = idx - cl * NCLS;
            float acc = b_p[n];
            const float* wrow = W_ph + n * HH;   // direct from global (L2-hot)
            const float* hcol = hs + cl;
            #pragma unroll 8
            for (int k = 0; k < HH; ++k)
                acc = fmaf(__ldg(wrow + k), hcol[k * H_PAD], acc);
            out[(cbase + cl) * NCLS + n] = acc;
        }
    }
}

extern "C" void kernel_launch(void* const* d_in, const int* in_sizes, int n_in,
                              void* d_out, int out_size) {
    const float* x      = (const float*)d_in[0];
    const float* h_init = (const float*)d_in[1];
    const float* W_hx   = (const float*)d_in[2];
    const float* W_hh   = (const float*)d_in[3];
    const float* b_h    = (const float*)d_in[4];
    const float* W_ph   = (const float*)d_in[5];
    const float* b_p    = (const float*)d_in[6];
    float* out = (float*)d_out;

    void* flagp = nullptr;
    cudaGetSymbolAddress(&flagp, g_flag);
    cudaMemsetAsync(flagp, 0, BGN * RGN * 32 * sizeof(unsigned), 0);

    cudaFuncSetAttribute(rnn_persistent,
                         cudaFuncAttributeMaxDynamicSharedMemorySize, SMEM_BYTES);

    rnn_persistent<<<NCTA, NTHR, SMEM_BYTES, 0>>>(x, h_init, W_hx, W_hh, b_h,
                                                  W_ph, b_p, out);
}